// round 5
// baseline (speedup 1.0000x reference)
#include <cuda_runtime.h>
#include <math.h>

#define BATCH 8
#define TT 96
#define NNODE 200
#define EMB 32
#define HID 32
#define HOR 24
#define FV 400
#define KEV 200              /* even-column K dim */
#define NSEQ (BATCH*NNODE)   /* 1600 */
#define ROWS (BATCH*TT)      /* 768  */
#define HMT 6400
#define NG (NNODE*96)        /* 19200: (node,gate) fused dim */

// ---- scratch (static device globals; no allocations allowed) ----
__device__ float g_q[ROWS*EMB];
__device__ float g_k[ROWS*EMB];
__device__ float g_E[ROWS*TT];
__device__ float g_att_e[ROWS*KEV];      // [768 x 200] attention (even) outputs
__device__ int   g_zf[BATCH*NNODE];      // per-(b,n) all-masked flag (rewritten each launch)
__device__ float g_vwe[HMT*KEV];         // packed even columns of v_w (5.1 MB)
__device__ float g_colsum[HMT];          // vb + sum of odd v_w columns
__device__ float g_W2[NG*KEV];           // fused (vwe x wih) weights, 15.4 MB
__device__ float g_GB[NG];               // fused bias
__device__ float g_GI[ROWS*NG];          // [ (b,t) x (n,g) ]  59 MB

__device__ __forceinline__ float sigf(float x){ return 1.0f/(1.0f + __expf(-x)); }
__device__ __forceinline__ float ftanh(float x){ return 2.0f*sigf(2.0f*x) - 1.0f; }

// ---------------------------------------------------------------------------
// K0: time embedding + q/k projections.  grid=768, 32 threads.
// ---------------------------------------------------------------------------
__global__ void k0_qk(const float* __restrict__ ts, const float* __restrict__ te_w,
                      const float* __restrict__ te_b, const float* __restrict__ q_w,
                      const float* __restrict__ q_b, const float* __restrict__ k_w){
    int row = blockIdx.x; int e = threadIdx.x;
    __shared__ float te[EMB];
    float v = ts[row]*te_w[e] + te_b[e];
    if (e > 0) v = sinf(v);
    te[e] = v; __syncthreads();
    float q = q_b[e], k = 0.f;
    #pragma unroll
    for (int i=0;i<EMB;i++){
        q = fmaf(te[i], q_w[e*EMB+i], q);
        k = fmaf(te[i], k_w[e*EMB+i], k);
    }
    g_q[row*EMB+e] = q;
    g_k[row*EMB+e] = k;
}

// ---------------------------------------------------------------------------
// K1: scores + row max + E=exp(s-M).  grid=768, 96 threads.
// ---------------------------------------------------------------------------
__global__ void k1_scores(){
    int row = blockIdx.x; int b = row/TT; int tid = threadIdx.x;
    __shared__ float qv[EMB];
    __shared__ float ks[TT*33];
    __shared__ float sbuf[TT];
    __shared__ float smax;
    if (tid < EMB) qv[tid] = g_q[row*EMB + tid];
    for (int idx = tid; idx < TT*EMB; idx += 96){
        int kk = idx >> 5, i = idx & 31;
        ks[kk*33 + i] = g_k[(b*TT + kk)*EMB + i];
    }
    __syncthreads();
    float s = 0.f;
    #pragma unroll
    for (int i=0;i<EMB;i++) s = fmaf(qv[i], ks[tid*33+i], s);
    s *= 0.17677669529663687f;
    sbuf[tid] = s; __syncthreads();
    if (tid < 32){
        float m = fmaxf(sbuf[tid], fmaxf(sbuf[tid+32], sbuf[tid+64]));
        #pragma unroll
        for (int o=16;o;o>>=1) m = fmaxf(m, __shfl_xor_sync(0xffffffffu, m, o));
        if (tid==0) smax = m;
    }
    __syncthreads();
    g_E[row*TT + tid] = __expf(s - smax);
}

// ---------------------------------------------------------------------------
// K2: masked softmax aggregation. grid=(25,8)=(n-chunk, b), 256 thr.
// Warp w owns node n0+w; lanes own queries {lane, lane+32, lane+64}.
// E cached in smem (pad 97). den==0 is per-(b,n) -> flag array (no atomics).
// ---------------------------------------------------------------------------
__global__ void __launch_bounds__(256)
k2_att(const float* __restrict__ x, const float* __restrict__ mask){
    int b = blockIdx.y, n0 = blockIdx.x*8;
    int tid = threadIdx.x, w = tid>>5, lane = tid&31;
    int n = n0 + w;
    __shared__ float Es[TT][97];
    __shared__ float smx[8][TT];
    __shared__ float smm[8][TT];
    __shared__ float ssx[8];
    for (int q=w; q<TT; q+=8){
        const float* er = g_E + (b*TT+q)*TT;
        Es[q][lane]    = er[lane];
        Es[q][lane+32] = er[lane+32];
        Es[q][lane+64] = er[lane+64];
    }
    float sx = 0.f;
    #pragma unroll
    for (int t=lane; t<TT; t+=32){
        float xv = x   [b*TT*NNODE + t*NNODE + n];
        float mv = mask[b*TT*NNODE + t*NNODE + n];
        smx[w][t] = mv*xv;
        smm[w][t] = mv;
        sx += xv;
    }
    #pragma unroll
    for (int o=16;o;o>>=1) sx += __shfl_xor_sync(0xffffffffu, sx, o);
    if (lane==0) ssx[w] = sx;
    __syncthreads();

    float n0a=0.f,n1a=0.f,n2a=0.f, d0=0.f,d1=0.f,d2=0.f;
    #pragma unroll 4
    for (int k=0;k<TT;k++){
        float mm = smm[w][k], mx = smx[w][k];
        float e0 = Es[lane][k], e1 = Es[lane+32][k], e2 = Es[lane+64][k];
        d0 += e0*mm; n0a = fmaf(e0, mx, n0a);
        d1 += e1*mm; n1a = fmaf(e1, mx, n1a);
        d2 += e2*mm; n2a = fmaf(e2, mx, n2a);
    }
    bool nz = (d0 > 0.f);            // same truth value for all queries
    float fb = ssx[w]*(1.0f/96.0f);
    g_att_e[(b*TT+lane   )*KEV + n] = nz ? n0a/d0 : fb;
    g_att_e[(b*TT+lane+32)*KEV + n] = nz ? n1a/d1 : fb;
    g_att_e[(b*TT+lane+64)*KEV + n] = nz ? n2a/d2 : fb;
    if (lane==0) g_zf[b*NNODE + n] = nz ? 0 : 1;
}

// ---------------------------------------------------------------------------
// K2b: pack even columns of v_w, colsum = vb + sum(odd columns).
// ---------------------------------------------------------------------------
__global__ void k2b_pack(const float* __restrict__ vw, const float* __restrict__ vb){
    int j = (blockIdx.x*256 + threadIdx.x) >> 5;
    int lane = threadIdx.x & 31;
    const float4* src = (const float4*)(vw + (size_t)j*FV);
    float os = 0.f;
    #pragma unroll
    for (int c=lane; c<100; c+=32){
        float4 v = src[c];
        *(float2*)&g_vwe[(size_t)j*KEV + 2*c] = make_float2(v.x, v.z);
        os += v.y + v.w;
    }
    #pragma unroll
    for (int o=16;o;o>>=1) os += __shfl_xor_sync(0xffffffffu, os, o);
    if (lane == 0) g_colsum[j] = vb[j] + os;
}

// ---------------------------------------------------------------------------
// KW: fuse GRU input weights into attention-V weights.
// W2[(n,g),k] = sum_i wih[g,i] * vwe[n*32+i, k];  GB[(n,g)] = wih.colsum + bih
// grid=200 (one per node), 256 threads.
// ---------------------------------------------------------------------------
__global__ void __launch_bounds__(256)
kW_fuse(const float* __restrict__ wih, const float* __restrict__ bih,
        const float* __restrict__ /*unused*/){
    int n = blockIdx.x;
    int tid = threadIdx.x;
    __shared__ float wsh[96*32];     // 12 KB
    __shared__ float vsh[32*201];    // 25.7 KB (padded rows)
    for (int idx=tid; idx<96*32; idx+=256) wsh[idx] = wih[idx];
    for (int idx=tid; idx<32*KEV; idx+=256){
        int i = idx/KEV, k = idx%KEV;
        vsh[i*201+k] = g_vwe[((size_t)n*32+i)*KEV + k];
    }
    __syncthreads();
    for (int out=tid; out<96*KEV; out+=256){
        int g = out/KEV, k = out - g*KEV;
        float acc = 0.f;
        #pragma unroll
        for (int i=0;i<32;i++) acc = fmaf(wsh[g*32+i], vsh[i*201+k], acc);
        g_W2[((size_t)n*96 + g)*KEV + k] = acc;
    }
    if (tid < 96){
        float gb = bih[tid];
        #pragma unroll
        for (int i=0;i<32;i++) gb = fmaf(wsh[tid*32+i], g_colsum[n*32+i], gb);
        g_GB[n*96 + tid] = gb;
    }
}

// ---------------------------------------------------------------------------
// KG: GI[768 x 19200] = att_e[768x200] @ W2[19200x200]^T + GB
// 128x128x8 double-buffered SGEMM, 256 threads, 8x8 per thread.
// ---------------------------------------------------------------------------
__global__ void __launch_bounds__(256,2)
kG_gemm(){
    __shared__ float As[2][8][128];
    __shared__ float Bs[2][8][128];
    int tid = threadIdx.x;
    int bn = blockIdx.x, bm = blockIdx.y;
    int warp = tid>>5, lane = tid&31;
    int tm = (warp>>1)*32 + ((lane>>3)<<2);
    int tn = (warp&1)*64  + ((lane&7)<<2);

    int lrow = tid>>1;
    int lk   = (tid&1)<<2;

    const float* Ag = g_att_e + (size_t)(bm*128 + lrow)*KEV + lk;
    const float* Bg = g_W2    + (size_t)(bn*128 + lrow)*KEV + lk;

    float4 a_st = *(const float4*)Ag;
    float4 b_st = *(const float4*)Bg;
    As[0][lk+0][lrow]=a_st.x; As[0][lk+1][lrow]=a_st.y;
    As[0][lk+2][lrow]=a_st.z; As[0][lk+3][lrow]=a_st.w;
    Bs[0][lk+0][lrow]=b_st.x; Bs[0][lk+1][lrow]=b_st.y;
    Bs[0][lk+2][lrow]=b_st.z; Bs[0][lk+3][lrow]=b_st.w;
    __syncthreads();

    float acc[8][8];
    #pragma unroll
    for (int i=0;i<8;i++)
        #pragma unroll
        for (int j=0;j<8;j++) acc[i][j]=0.f;

    int cur = 0;
    #pragma unroll 1
    for (int it=0; it<25; ++it){
        if (it < 24){
            a_st = *(const float4*)(Ag + (it+1)*8);
            b_st = *(const float4*)(Bg + (it+1)*8);
        }
        #pragma unroll
        for (int k=0;k<8;k++){
            float4 a0 = *(const float4*)&As[cur][k][tm];
            float4 a1 = *(const float4*)&As[cur][k][tm+16];
            float4 b0 = *(const float4*)&Bs[cur][k][tn];
            float4 b1 = *(const float4*)&Bs[cur][k][tn+32];
            float ar[8] = {a0.x,a0.y,a0.z,a0.w,a1.x,a1.y,a1.z,a1.w};
            float br[8] = {b0.x,b0.y,b0.z,b0.w,b1.x,b1.y,b1.z,b1.w};
            #pragma unroll
            for (int i=0;i<8;i++)
                #pragma unroll
                for (int j=0;j<8;j++)
                    acc[i][j] = fmaf(ar[i], br[j], acc[i][j]);
        }
        if (it < 24){
            int nxt = cur^1;
            As[nxt][lk+0][lrow]=a_st.x; As[nxt][lk+1][lrow]=a_st.y;
            As[nxt][lk+2][lrow]=a_st.z; As[nxt][lk+3][lrow]=a_st.w;
            Bs[nxt][lk+0][lrow]=b_st.x; Bs[nxt][lk+1][lrow]=b_st.y;
            Bs[nxt][lk+2][lrow]=b_st.z; Bs[nxt][lk+3][lrow]=b_st.w;
            __syncthreads();
            cur = nxt;
        }
    }

    int col0 = bn*128 + tn;
    float4 cs0 = *(const float4*)(g_GB + col0);
    float4 cs1 = *(const float4*)(g_GB + col0 + 32);
    const int ro[8] = {0,1,2,3,16,17,18,19};
    #pragma unroll
    for (int i=0;i<8;i++){
        int row = bm*128 + tm + ro[i];
        float4 o0, o1;
        o0.x = acc[i][0]+cs0.x; o0.y = acc[i][1]+cs0.y;
        o0.z = acc[i][2]+cs0.z; o0.w = acc[i][3]+cs0.w;
        o1.x = acc[i][4]+cs1.x; o1.y = acc[i][5]+cs1.y;
        o1.z = acc[i][6]+cs1.z; o1.w = acc[i][7]+cs1.w;
        *(float4*)(g_GI + (size_t)row*NG + col0)      = o0;
        *(float4*)(g_GI + (size_t)row*NG + col0 + 32) = o1;
    }
}

// ---------------------------------------------------------------------------
// K5: GRU recurrence (warp = sequence) with prefetch + fused MLP decoder.
// ---------------------------------------------------------------------------
__global__ void __launch_bounds__(256)
k5_gru(const float* __restrict__ whh, const float* __restrict__ bhh,
       const float* __restrict__ mlp_w, const float* __restrict__ mlp_b,
       const float* __restrict__ out_w, const float* __restrict__ out_b,
       const float* __restrict__ wih, const float* __restrict__ vw,
       float* __restrict__ out){
    int wid = threadIdx.x >> 5;
    int j   = threadIdx.x & 31;
    int seq = blockIdx.x*8 + wid;
    int b = seq / NNODE, n = seq % NNODE;

    float wr[32], wz[32], wn[32];
    #pragma unroll
    for (int i=0;i<32;i++){
        wr[i] = whh[j*32+i];
        wz[i] = whh[(32+j)*32+i];
        wn[i] = whh[(64+j)*32+i];
    }
    float bhr = bhh[j], bhz = bhh[32+j], bhn = bhh[64+j];

    // all-masked-node correction (exact; probability ~2^-96 per node)
    float c0=0.f, c1=0.f, c2=0.f;
    {
        int anyz = 0;
        for (int i=j; i<NNODE; i+=32) anyz |= g_zf[b*NNODE+i];
        anyz = __reduce_or_sync(0xffffffffu, anyz);
        if (anyz){
            for (int n0=0;n0<NNODE;n0++){
                if (g_zf[b*NNODE+n0]){
                    #pragma unroll
                    for (int i=0;i<32;i++){
                        float vv = vw[((size_t)n*32+i)*FV + 2*n0 + 1];
                        c0 = fmaf(wih[j*32+i],       vv, c0);
                        c1 = fmaf(wih[(32+j)*32+i],  vv, c1);
                        c2 = fmaf(wih[(64+j)*32+i],  vv, c2);
                    }
                }
            }
        }
    }

    const float* base = g_GI + (size_t)b*TT*NG + n*96;
    float a0 = base[j], a1 = base[32+j], a2 = base[64+j];

    float h = 0.f;
    for (int t=0;t<TT;t++){
        const float* nx = base + (size_t)((t<TT-1)? t+1 : t)*NG;
        float p0 = nx[j], p1 = nx[32+j], p2 = nx[64+j];
        float hr=0.f, hz=0.f, hn=0.f;
        #pragma unroll
        for (int i=0;i<32;i++){
            float hv = __shfl_sync(0xffffffffu, h, i);
            hr = fmaf(wr[i], hv, hr);
            hz = fmaf(wz[i], hv, hz);
            hn = fmaf(wn[i], hv, hn);
        }
        float r  = sigf(a0 - c0 + hr + bhr);
        float z  = sigf(a1 - c1 + hz + bhz);
        float nn = ftanh(a2 - c2 + r*(hn + bhn));
        h = (1.f - z)*nn + z*h;
        a0 = p0; a1 = p1; a2 = p2;
    }

    float h2 = mlp_b[j];
    #pragma unroll
    for (int i=0;i<32;i++)
        h2 = fmaf(mlp_w[j*32+i], __shfl_sync(0xffffffffu, h, i), h2);
    h2 = fmaxf(h2, 0.f);

    float y = (j < HOR) ? out_b[j] : 0.f;
    #pragma unroll
    for (int i=0;i<32;i++){
        float v = __shfl_sync(0xffffffffu, h2, i);
        if (j < HOR) y = fmaf(out_w[j*32+i], v, y);
    }
    if (j < HOR) out[((size_t)b*HOR + j)*NNODE + n] = y;
}

// ---------------------------------------------------------------------------
extern "C" void kernel_launch(void* const* d_in, const int* in_sizes, int n_in,
                              void* d_out, int out_size){
    const float* x    = (const float*)d_in[0];
    const float* mask = (const float*)d_in[2];
    const float* ts   = (const float*)d_in[3];
    const float* te_w = (const float*)d_in[4];
    const float* te_b = (const float*)d_in[5];
    const float* q_w  = (const float*)d_in[6];
    const float* q_b  = (const float*)d_in[7];
    const float* k_w  = (const float*)d_in[8];
    const float* v_w  = (const float*)d_in[9];
    const float* v_b  = (const float*)d_in[10];
    const float* wih  = (const float*)d_in[11];
    const float* whh  = (const float*)d_in[12];
    const float* bih  = (const float*)d_in[13];
    const float* bhh  = (const float*)d_in[14];
    const float* mlpw = (const float*)d_in[15];
    const float* mlpb = (const float*)d_in[16];
    const float* outw = (const float*)d_in[17];
    const float* outb = (const float*)d_in[18];
    float* out = (float*)d_out;

    k2b_pack<<<800, 256>>>(v_w, v_b);
    k0_qk<<<ROWS, 32>>>(ts, te_w, te_b, q_w, q_b, k_w);
    k1_scores<<<ROWS, 96>>>();
    kW_fuse<<<NNODE, 256>>>(wih, bih, nullptr);
    k2_att<<<dim3(25, BATCH), 256>>>(x, mask);
    kG_gemm<<<dim3(NG/128, ROWS/128), 256>>>();
    k5_gru<<<NSEQ/8, 256>>>(whh, bhh, mlpw, mlpb, outw, outb, wih, v_w, out);
}

// round 6
// speedup vs baseline: 1.2150x; 1.2150x over previous
#include <cuda_runtime.h>
#include <math.h>

#define BATCH 8
#define TT 96
#define NNODE 200
#define EMB 32
#define HID 32
#define HOR 24
#define FV 400
#define KEV 200              /* even-column K dim */
#define NSEQ (BATCH*NNODE)   /* 1600 */
#define ROWS (BATCH*TT)      /* 768  */
#define HMT 6400

// ---- scratch (static device globals; no allocations allowed) ----
__device__ float g_q[ROWS*EMB];
__device__ float g_k[ROWS*EMB];
__device__ float g_E[ROWS*TT];
__device__ float g_att_e[ROWS*KEV];      // [768 x 200] attention (even) outputs
__device__ int   g_zf[BATCH*NNODE];      // per-(b,n) all-masked flag (rewritten each launch)
__device__ float g_vwe[HMT*KEV];         // packed even columns of v_w (5.1 MB)
__device__ float g_colsum[HMT];          // vb + sum of odd v_w columns
__device__ float g_Y[ROWS*HMT];          // mtan output, 19.6 MB

__device__ __forceinline__ float sigf(float x){ return 1.0f/(1.0f + __expf(-x)); }
__device__ __forceinline__ float ftanh(float x){ return 2.0f*sigf(2.0f*x) - 1.0f; }

// ---------------------------------------------------------------------------
// K0: time embedding + q/k projections.  grid=768, 32 threads.
// ---------------------------------------------------------------------------
__global__ void k0_qk(const float* __restrict__ ts, const float* __restrict__ te_w,
                      const float* __restrict__ te_b, const float* __restrict__ q_w,
                      const float* __restrict__ q_b, const float* __restrict__ k_w){
    int row = blockIdx.x; int e = threadIdx.x;
    __shared__ float te[EMB];
    float v = ts[row]*te_w[e] + te_b[e];
    if (e > 0) v = sinf(v);
    te[e] = v; __syncthreads();
    float q = q_b[e], k = 0.f;
    #pragma unroll
    for (int i=0;i<EMB;i++){
        q = fmaf(te[i], q_w[e*EMB+i], q);
        k = fmaf(te[i], k_w[e*EMB+i], k);
    }
    g_q[row*EMB+e] = q;
    g_k[row*EMB+e] = k;
}

// ---------------------------------------------------------------------------
// K1: scores + row max + E=exp(s-M).  grid=768, 96 threads.
// ---------------------------------------------------------------------------
__global__ void k1_scores(){
    int row = blockIdx.x; int b = row/TT; int tid = threadIdx.x;
    __shared__ float qv[EMB];
    __shared__ float ks[TT*33];
    __shared__ float sbuf[TT];
    __shared__ float smax;
    if (tid < EMB) qv[tid] = g_q[row*EMB + tid];
    for (int idx = tid; idx < TT*EMB; idx += 96){
        int kk = idx >> 5, i = idx & 31;
        ks[kk*33 + i] = g_k[(b*TT + kk)*EMB + i];
    }
    __syncthreads();
    float s = 0.f;
    #pragma unroll
    for (int i=0;i<EMB;i++) s = fmaf(qv[i], ks[tid*33+i], s);
    s *= 0.17677669529663687f;
    sbuf[tid] = s; __syncthreads();
    if (tid < 32){
        float m = fmaxf(sbuf[tid], fmaxf(sbuf[tid+32], sbuf[tid+64]));
        #pragma unroll
        for (int o=16;o;o>>=1) m = fmaxf(m, __shfl_xor_sync(0xffffffffu, m, o));
        if (tid==0) smax = m;
    }
    __syncthreads();
    g_E[row*TT + tid] = __expf(s - smax);
}

// ---------------------------------------------------------------------------
// K2: masked softmax aggregation. grid=(25,8)=(n-chunk, b), 256 thr.
// Warp w owns node n0+w; lanes own queries {lane, lane+32, lane+64}.
// ---------------------------------------------------------------------------
__global__ void __launch_bounds__(256)
k2_att(const float* __restrict__ x, const float* __restrict__ mask){
    int b = blockIdx.y, n0 = blockIdx.x*8;
    int tid = threadIdx.x, w = tid>>5, lane = tid&31;
    int n = n0 + w;
    __shared__ float Es[TT][97];
    __shared__ float smx[8][TT];
    __shared__ float smm[8][TT];
    __shared__ float ssx[8];
    for (int q=w; q<TT; q+=8){
        const float* er = g_E + (b*TT+q)*TT;
        Es[q][lane]    = er[lane];
        Es[q][lane+32] = er[lane+32];
        Es[q][lane+64] = er[lane+64];
    }
    float sx = 0.f;
    #pragma unroll
    for (int t=lane; t<TT; t+=32){
        float xv = x   [b*TT*NNODE + t*NNODE + n];
        float mv = mask[b*TT*NNODE + t*NNODE + n];
        smx[w][t] = mv*xv;
        smm[w][t] = mv;
        sx += xv;
    }
    #pragma unroll
    for (int o=16;o;o>>=1) sx += __shfl_xor_sync(0xffffffffu, sx, o);
    if (lane==0) ssx[w] = sx;
    __syncthreads();

    float n0a=0.f,n1a=0.f,n2a=0.f, d0=0.f,d1=0.f,d2=0.f;
    #pragma unroll 4
    for (int k=0;k<TT;k++){
        float mm = smm[w][k], mx = smx[w][k];
        float e0 = Es[lane][k], e1 = Es[lane+32][k], e2 = Es[lane+64][k];
        d0 += e0*mm; n0a = fmaf(e0, mx, n0a);
        d1 += e1*mm; n1a = fmaf(e1, mx, n1a);
        d2 += e2*mm; n2a = fmaf(e2, mx, n2a);
    }
    bool nz = (d0 > 0.f);            // same truth value for all queries of (b,n)
    float fb = ssx[w]*(1.0f/96.0f);
    g_att_e[(b*TT+lane   )*KEV + n] = nz ? n0a/d0 : fb;
    g_att_e[(b*TT+lane+32)*KEV + n] = nz ? n1a/d1 : fb;
    g_att_e[(b*TT+lane+64)*KEV + n] = nz ? n2a/d2 : fb;
    if (lane==0) g_zf[b*NNODE + n] = nz ? 0 : 1;
}

// ---------------------------------------------------------------------------
// K2b: pack even columns of v_w, colsum = vb + sum(odd columns).
// ---------------------------------------------------------------------------
__global__ void k2b_pack(const float* __restrict__ vw, const float* __restrict__ vb){
    int j = (blockIdx.x*256 + threadIdx.x) >> 5;
    int lane = threadIdx.x & 31;
    const float4* src = (const float4*)(vw + (size_t)j*FV);
    float os = 0.f;
    #pragma unroll
    for (int c=lane; c<100; c+=32){
        float4 v = src[c];
        *(float2*)&g_vwe[(size_t)j*KEV + 2*c] = make_float2(v.x, v.z);
        os += v.y + v.w;
    }
    #pragma unroll
    for (int o=16;o;o>>=1) os += __shfl_xor_sync(0xffffffffu, os, o);
    if (lane == 0) g_colsum[j] = vb[j] + os;
}

// ---------------------------------------------------------------------------
// K3: Y[768x6400] = att_e[768x200] @ vwe[6400x200]^T + colsum
// 128x128x8 double-buffered SGEMM, 256 threads, 8x8 per thread.
// (all-masked correction is applied downstream in k5, not here)
// ---------------------------------------------------------------------------
__global__ void __launch_bounds__(256,2)
k3_vgemm(){
    __shared__ float As[2][8][128];
    __shared__ float Bs[2][8][128];
    int tid = threadIdx.x;
    int bn = blockIdx.x, bm = blockIdx.y;
    int warp = tid>>5, lane = tid&31;
    int tm = (warp>>1)*32 + ((lane>>3)<<2);
    int tn = (warp&1)*64  + ((lane&7)<<2);

    int lrow = tid>>1;
    int lk   = (tid&1)<<2;

    const float* Ag = g_att_e + (size_t)(bm*128 + lrow)*KEV + lk;
    const float* Bg = g_vwe   + (size_t)(bn*128 + lrow)*KEV + lk;

    float4 a_st = *(const float4*)Ag;
    float4 b_st = *(const float4*)Bg;
    As[0][lk+0][lrow]=a_st.x; As[0][lk+1][lrow]=a_st.y;
    As[0][lk+2][lrow]=a_st.z; As[0][lk+3][lrow]=a_st.w;
    Bs[0][lk+0][lrow]=b_st.x; Bs[0][lk+1][lrow]=b_st.y;
    Bs[0][lk+2][lrow]=b_st.z; Bs[0][lk+3][lrow]=b_st.w;
    __syncthreads();

    float acc[8][8];
    #pragma unroll
    for (int i=0;i<8;i++)
        #pragma unroll
        for (int j=0;j<8;j++) acc[i][j]=0.f;

    int cur = 0;
    #pragma unroll 1
    for (int it=0; it<25; ++it){
        if (it < 24){
            a_st = *(const float4*)(Ag + (it+1)*8);
            b_st = *(const float4*)(Bg + (it+1)*8);
        }
        #pragma unroll
        for (int k=0;k<8;k++){
            float4 a0 = *(const float4*)&As[cur][k][tm];
            float4 a1 = *(const float4*)&As[cur][k][tm+16];
            float4 b0 = *(const float4*)&Bs[cur][k][tn];
            float4 b1 = *(const float4*)&Bs[cur][k][tn+32];
            float ar[8] = {a0.x,a0.y,a0.z,a0.w,a1.x,a1.y,a1.z,a1.w};
            float br[8] = {b0.x,b0.y,b0.z,b0.w,b1.x,b1.y,b1.z,b1.w};
            #pragma unroll
            for (int i=0;i<8;i++)
                #pragma unroll
                for (int j=0;j<8;j++)
                    acc[i][j] = fmaf(ar[i], br[j], acc[i][j]);
        }
        if (it < 24){
            int nxt = cur^1;
            As[nxt][lk+0][lrow]=a_st.x; As[nxt][lk+1][lrow]=a_st.y;
            As[nxt][lk+2][lrow]=a_st.z; As[nxt][lk+3][lrow]=a_st.w;
            Bs[nxt][lk+0][lrow]=b_st.x; Bs[nxt][lk+1][lrow]=b_st.y;
            Bs[nxt][lk+2][lrow]=b_st.z; Bs[nxt][lk+3][lrow]=b_st.w;
            __syncthreads();
            cur = nxt;
        }
    }

    int col0 = bn*128 + tn;
    float4 cs0 = *(const float4*)(g_colsum + col0);
    float4 cs1 = *(const float4*)(g_colsum + col0 + 32);
    const int ro[8] = {0,1,2,3,16,17,18,19};
    #pragma unroll
    for (int i=0;i<8;i++){
        int row = bm*128 + tm + ro[i];
        float4 o0, o1;
        o0.x = acc[i][0]+cs0.x; o0.y = acc[i][1]+cs0.y;
        o0.z = acc[i][2]+cs0.z; o0.w = acc[i][3]+cs0.w;
        o1.x = acc[i][4]+cs1.x; o1.y = acc[i][5]+cs1.y;
        o1.z = acc[i][6]+cs1.z; o1.w = acc[i][7]+cs1.w;
        *(float4*)(g_Y + (size_t)row*HMT + col0)      = o0;
        *(float4*)(g_Y + (size_t)row*HMT + col0 + 32) = o1;
    }
}

// ---------------------------------------------------------------------------
// K5: GRU with fused input projection (gi = wih@x computed in-warp) +
// depth-4 x prefetch + fused MLP decoder.
// warp = one (b,n) sequence; lane j = hidden unit j.
// grid = 400 blocks x 128 threads (4 warps/block).
// ---------------------------------------------------------------------------
__global__ void __launch_bounds__(128)
k5_gru(const float* __restrict__ whh, const float* __restrict__ bhh,
       const float* __restrict__ wih, const float* __restrict__ bih,
       const float* __restrict__ mlp_w, const float* __restrict__ mlp_b,
       const float* __restrict__ out_w, const float* __restrict__ out_b,
       const float* __restrict__ vw,
       float* __restrict__ out){
    int wid = threadIdx.x >> 5;
    int j   = threadIdx.x & 31;
    int seq = blockIdx.x*4 + wid;
    int b = seq / NNODE, n = seq % NNODE;

    // recurrent weights (rows j, 32+j, 64+j) and input weights, in registers
    float ur[32], uz[32], un[32], wr[32], wz[32], wn[32];
    #pragma unroll
    for (int i=0;i<32;i++){
        ur[i] = whh[j*32+i];
        uz[i] = whh[(32+j)*32+i];
        un[i] = whh[(64+j)*32+i];
        wr[i] = wih[j*32+i];
        wz[i] = wih[(32+j)*32+i];
        wn[i] = wih[(64+j)*32+i];
    }

    // all-masked-node correction (exact; probability ~2^-96 per node)
    float c0=0.f, c1=0.f, c2=0.f;
    {
        int anyz = 0;
        for (int i=j; i<NNODE; i+=32) anyz |= g_zf[b*NNODE+i];
        anyz = __reduce_or_sync(0xffffffffu, anyz);
        if (anyz){
            for (int n0=0;n0<NNODE;n0++){
                if (g_zf[b*NNODE+n0]){
                    #pragma unroll
                    for (int i=0;i<32;i++){
                        float vv = vw[((size_t)n*32+i)*FV + 2*n0 + 1];
                        c0 = fmaf(wr[i], vv, c0);
                        c1 = fmaf(wz[i], vv, c1);
                        c2 = fmaf(wn[i], vv, c2);
                    }
                }
            }
        }
    }
    float cr  = bih[j]     - c0 + bhh[j];
    float cz  = bih[32+j]  - c1 + bhh[32+j];
    float cn  = bih[64+j]  - c2;
    float bn2 = bhh[64+j];

    const float* xb = g_Y + (size_t)b*TT*HMT + n*HID + j;   // + t*HMT

    float xq[4];
    #pragma unroll
    for (int d=0; d<4; d++) xq[d] = xb[(size_t)d*HMT];

    float h = 0.f;
    #pragma unroll 2
    for (int t=0;t<TT;t++){
        float xc = xq[t&3];
        if (t+4 < TT) xq[t&3] = xb[(size_t)(t+4)*HMT];
        float gr=0.f, gz=0.f, gn=0.f, hr=0.f, hz=0.f, hn=0.f;
        #pragma unroll
        for (int i=0;i<32;i++){
            float xv = __shfl_sync(0xffffffffu, xc, i);
            float hv = __shfl_sync(0xffffffffu, h,  i);
            gr = fmaf(wr[i], xv, gr);
            gz = fmaf(wz[i], xv, gz);
            gn = fmaf(wn[i], xv, gn);
            hr = fmaf(ur[i], hv, hr);
            hz = fmaf(uz[i], hv, hz);
            hn = fmaf(un[i], hv, hn);
        }
        float r  = sigf(gr + hr + cr);
        float z  = sigf(gz + hz + cz);
        float nn = ftanh(gn + cn + r*(hn + bn2));
        h = (1.f - z)*nn + z*h;
    }

    float h2 = mlp_b[j];
    #pragma unroll
    for (int i=0;i<32;i++)
        h2 = fmaf(mlp_w[j*32+i], __shfl_sync(0xffffffffu, h, i), h2);
    h2 = fmaxf(h2, 0.f);

    float y = (j < HOR) ? out_b[j] : 0.f;
    #pragma unroll
    for (int i=0;i<32;i++){
        float v = __shfl_sync(0xffffffffu, h2, i);
        if (j < HOR) y = fmaf(out_w[j*32+i], v, y);
    }
    if (j < HOR) out[((size_t)b*HOR + j)*NNODE + n] = y;
}

// ---------------------------------------------------------------------------
extern "C" void kernel_launch(void* const* d_in, const int* in_sizes, int n_in,
                              void* d_out, int out_size){
    const float* x    = (const float*)d_in[0];
    const float* mask = (const float*)d_in[2];
    const float* ts   = (const float*)d_in[3];
    const float* te_w = (const float*)d_in[4];
    const float* te_b = (const float*)d_in[5];
    const float* q_w  = (const float*)d_in[6];
    const float* q_b  = (const float*)d_in[7];
    const float* k_w  = (const float*)d_in[8];
    const float* v_w  = (const float*)d_in[9];
    const float* v_b  = (const float*)d_in[10];
    const float* wih  = (const float*)d_in[11];
    const float* whh  = (const float*)d_in[12];
    const float* bih  = (const float*)d_in[13];
    const float* bhh  = (const float*)d_in[14];
    const float* mlpw = (const float*)d_in[15];
    const float* mlpb = (const float*)d_in[16];
    const float* outw = (const float*)d_in[17];
    const float* outb = (const float*)d_in[18];
    float* out = (float*)d_out;

    k2b_pack<<<800, 256>>>(v_w, v_b);
    k0_qk<<<ROWS, 32>>>(ts, te_w, te_b, q_w, q_b, k_w);
    k1_scores<<<ROWS, 96>>>();
    k2_att<<<dim3(25, BATCH), 256>>>(x, mask);
    k3_vgemm<<<dim3(HMT/128, ROWS/128), 256>>>();
    k5_gru<<<NSEQ/4, 128>>>(whh, bhh, wih, bih, mlpw, mlpb, outw, outb, v_w, out);
}